// round 1
// baseline (speedup 1.0000x reference)
#include <cuda_runtime.h>

#define BATCH 4096
#define NCENT 2048
#define DX    32
#define RNK   64
#define DD    512
#define KSPL  4
#define DCHUNK (DD / KSPL)   // 128

// Scratch (static __device__ — no allocation at runtime)
__device__ float g_phiT[NCENT * BATCH];        // 32 MB, phiT[c][b]
__device__ float g_R0[BATCH * RNK];
__device__ float g_t1[BATCH * RNK];
__device__ float g_t2[BATCH * RNK];
__device__ float g_part[KSPL * BATCH * RNK];   // split-K partials

// ---------------------------------------------------------------------------
// phi kernel: phiT[c][b] = exp(-(sqrt(max(sq,0))/exp(ls[c]))^2)
// sq = ||x_b||^2 + ||c_c||^2 - 2 x_b . c_c
// Tile 64c x 64b per block, 256 threads, 4x4 register tile.
// ---------------------------------------------------------------------------
__global__ __launch_bounds__(256) void phi_kernel(const float* __restrict__ X,
                                                  const float* __restrict__ Cn,
                                                  const float* __restrict__ LS)
{
    __shared__ float XsT[DX][64];
    __shared__ float CsT[DX][64];
    __shared__ float xn[64], cn[64], sg[64];
    const int t  = threadIdx.x;
    const int c0 = blockIdx.x * 64;
    const int b0 = blockIdx.y * 64;

    for (int x = t; x < 64 * DX; x += 256) {
        int r = x >> 5, k = x & 31;
        XsT[k][r] = X[(b0 + r) * DX + k];
        CsT[k][r] = Cn[(c0 + r) * DX + k];
    }
    if (t < 64) sg[t] = expf(LS[c0 + t]);
    __syncthreads();

    if (t < 64) {
        float s = 0.f;
        #pragma unroll
        for (int k = 0; k < DX; k++) { float v = XsT[k][t]; s += v * v; }
        xn[t] = s;
    } else if (t < 128) {
        int c = t - 64; float s = 0.f;
        #pragma unroll
        for (int k = 0; k < DX; k++) { float v = CsT[k][c]; s += v * v; }
        cn[c] = s;
    }
    __syncthreads();

    const int tb = (t & 15) * 4;
    const int tc = (t >> 4) * 4;
    float acc[4][4];
    #pragma unroll
    for (int i = 0; i < 4; i++)
        #pragma unroll
        for (int j = 0; j < 4; j++) acc[i][j] = 0.f;

    #pragma unroll
    for (int k = 0; k < DX; k++) {
        float4 xv = *reinterpret_cast<const float4*>(&XsT[k][tb]);
        float4 cv = *reinterpret_cast<const float4*>(&CsT[k][tc]);
        float xa[4] = {xv.x, xv.y, xv.z, xv.w};
        float ca[4] = {cv.x, cv.y, cv.z, cv.w};
        #pragma unroll
        for (int ci = 0; ci < 4; ci++)
            #pragma unroll
            for (int bi = 0; bi < 4; bi++)
                acc[ci][bi] += ca[ci] * xa[bi];
    }

    #pragma unroll
    for (int ci = 0; ci < 4; ci++) {
        float inv_s = 1.0f / sg[tc + ci];
        float o[4];
        #pragma unroll
        for (int bi = 0; bi < 4; bi++) {
            float sq = xn[tb + bi] + cn[tc + ci] - 2.0f * acc[ci][bi];
            float dist = sqrtf(fmaxf(sq, 0.0f)) * inv_s;
            o[bi] = expf(-dist * dist);
        }
        float4 ov = make_float4(o[0], o[1], o[2], o[3]);
        *reinterpret_cast<float4*>(&g_phiT[(size_t)(c0 + tc + ci) * BATCH + b0 + tb]) = ov;
    }
}

// ---------------------------------------------------------------------------
// R0 = Phi0 @ G0 : M=4096, N=64, K=512. Tile 64x64, 256 threads, 4x4 reg tile.
// ---------------------------------------------------------------------------
__global__ __launch_bounds__(256) void r0_kernel(const float* __restrict__ G0)
{
    __shared__ float As[32][64];   // As[k][b] from phiT rows 0..511
    __shared__ float Bs[32][64];   // Bs[k][i] from G0
    const int t  = threadIdx.x;
    const int b0 = blockIdx.x * 64;
    const int tb = (t & 15) * 4;
    const int tj = (t >> 4) * 4;
    float acc[4][4] = {};

    for (int d0 = 0; d0 < DD; d0 += 32) {
        __syncthreads();
        for (int x = t; x < 32 * 64; x += 256) {
            int k = x >> 6, r = x & 63;
            As[k][r] = g_phiT[(size_t)(d0 + k) * BATCH + b0 + r];
            Bs[k][r] = G0[(d0 + k) * RNK + r];
        }
        __syncthreads();
        #pragma unroll
        for (int k = 0; k < 32; k++) {
            float4 a = *reinterpret_cast<const float4*>(&As[k][tb]);
            float4 b = *reinterpret_cast<const float4*>(&Bs[k][tj]);
            float aa[4] = {a.x, a.y, a.z, a.w};
            float bb[4] = {b.x, b.y, b.z, b.w};
            #pragma unroll
            for (int bi = 0; bi < 4; bi++)
                #pragma unroll
                for (int ji = 0; ji < 4; ji++)
                    acc[bi][ji] += aa[bi] * bb[ji];
        }
    }
    #pragma unroll
    for (int bi = 0; bi < 4; bi++)
        #pragma unroll
        for (int ji = 0; ji < 4; ji++)
            g_R0[(b0 + tb + bi) * RNK + tj + ji] = acc[bi][ji];
}

// ---------------------------------------------------------------------------
// Stage GEMM: Out[b,j] = sum_d Phi[b,cbase+d] * sum_i V[b,i] * G[i,d,j]
// A generated on the fly: per d, As[i][b] = V[b][i] * Phi[b][d].
// Tile: 128 b-rows x NOUT cols per block; split-K over d (KSPL chunks).
// 256 threads; each thread: 8b x NJ register tile (b's at tb..tb+3, tb+64..+67).
// ---------------------------------------------------------------------------
template<int NOUT, int NJ>
__global__ __launch_bounds__(256) void stage_kernel(const float* __restrict__ V,
                                                    const float* __restrict__ G,
                                                    int cbase)
{
    extern __shared__ float sm[];
    float* As = sm;               // [RNK][128]
    float* Bs = sm + RNK * 128;   // [RNK][NOUT]

    const int t  = threadIdx.x;
    const int b0 = blockIdx.x * 128;
    const int d0 = blockIdx.y * DCHUNK;
    const int bA = t & 127;
    const int i0 = t >> 7;        // 0 or 1

    // Stage V into As (conflict-free STS), then cache this thread's column in regs.
    for (int x = t; x < 128 * RNK; x += 256) {
        int b = x & 127, i = x >> 7;
        As[i * 128 + b] = V[(b0 + b) * RNK + i];
    }
    __syncthreads();
    float vreg[32];
    #pragma unroll
    for (int k = 0; k < 32; k++) vreg[k] = As[(i0 + 2 * k) * 128 + bA];
    __syncthreads();

    const int tb = (t & 15) * 4;
    const int tj = (t >> 4) * NJ;
    float acc[8][NJ];
    #pragma unroll
    for (int r = 0; r < 8; r++)
        #pragma unroll
        for (int j = 0; j < NJ; j++) acc[r][j] = 0.f;

    const float4* Gv = reinterpret_cast<const float4*>(G);

    for (int dl = 0; dl < DCHUNK; ++dl) {
        const int d = d0 + dl;
        // Load B tile: G[i][d][0..NOUT) for all i (rows contiguous, coalesced)
        for (int x = t; x < RNK * (NOUT / 4); x += 256) {
            int i  = x / (NOUT / 4);
            int jv = x - i * (NOUT / 4);
            reinterpret_cast<float4*>(Bs)[i * (NOUT / 4) + jv] =
                Gv[((size_t)i * DD + d) * (NOUT / 4) + jv];
        }
        // Generate A tile for this d: As[i][b] = V[b][i] * phi[b][d]
        float p = g_phiT[(size_t)(cbase + d) * BATCH + b0 + bA];
        #pragma unroll
        for (int k = 0; k < 32; k++)
            As[(i0 + 2 * k) * 128 + bA] = vreg[k] * p;
        __syncthreads();

        #pragma unroll 8
        for (int i = 0; i < RNK; i++) {
            float4 a0 = *reinterpret_cast<const float4*>(&As[i * 128 + tb]);
            float4 a1 = *reinterpret_cast<const float4*>(&As[i * 128 + tb + 64]);
            float bf[NJ];
            #pragma unroll
            for (int j = 0; j < NJ; j++) bf[j] = Bs[i * NOUT + tj + j];
            float av[8] = {a0.x, a0.y, a0.z, a0.w, a1.x, a1.y, a1.z, a1.w};
            #pragma unroll
            for (int r = 0; r < 8; r++)
                #pragma unroll
                for (int j = 0; j < NJ; j++)
                    acc[r][j] += av[r] * bf[j];
        }
        __syncthreads();
    }

    float* outp = g_part + (size_t)blockIdx.y * (BATCH * NOUT);
    #pragma unroll
    for (int r = 0; r < 8; r++) {
        int b = b0 + ((r < 4) ? (tb + r) : (64 + tb + (r - 4)));
        #pragma unroll
        for (int j = 0; j < NJ; j++)
            outp[b * NOUT + tj + j] = acc[r][j];
    }
}

// ---------------------------------------------------------------------------
// Deterministic split-K reduction
// ---------------------------------------------------------------------------
__global__ void combine_kernel(float* __restrict__ dst, int nout)
{
    int n = BATCH * nout;
    int x = blockIdx.x * blockDim.x + threadIdx.x;
    if (x < n) {
        float s = 0.f;
        #pragma unroll
        for (int ks = 0; ks < KSPL; ks++) s += g_part[(size_t)ks * n + x];
        dst[x] = s;
    }
}

// ---------------------------------------------------------------------------
extern "C" void kernel_launch(void* const* d_in, const int* in_sizes, int n_in,
                              void* d_out, int out_size)
{
    const float* X  = (const float*)d_in[0];
    const float* Cn = (const float*)d_in[1];
    const float* LS = (const float*)d_in[2];
    const float* G0 = (const float*)d_in[3];
    const float* G1 = (const float*)d_in[4];
    const float* G2 = (const float*)d_in[5];
    const float* G3 = (const float*)d_in[6];
    float* out = (float*)d_out;

    void *pR0, *pT1, *pT2;
    cudaGetSymbolAddress(&pR0, g_R0);
    cudaGetSymbolAddress(&pT1, g_t1);
    cudaGetSymbolAddress(&pT2, g_t2);

    const size_t smem64 = (RNK * 128 + RNK * 64) * sizeof(float);  // 49152 B
    const size_t smem32 = (RNK * 128 + RNK * 32) * sizeof(float);  // 40960 B
    cudaFuncSetAttribute(stage_kernel<64, 4>,
                         cudaFuncAttributeMaxDynamicSharedMemorySize, (int)smem64);
    cudaFuncSetAttribute(stage_kernel<32, 2>,
                         cudaFuncAttributeMaxDynamicSharedMemorySize, (int)smem32);

    phi_kernel<<<dim3(NCENT / 64, BATCH / 64), 256>>>(X, Cn, LS);
    r0_kernel<<<BATCH / 64, 256>>>(G0);

    stage_kernel<64, 4><<<dim3(BATCH / 128, KSPL), 256, smem64>>>((const float*)pR0, G1, 512);
    combine_kernel<<<(BATCH * 64 + 255) / 256, 256>>>((float*)pT1, 64);

    stage_kernel<64, 4><<<dim3(BATCH / 128, KSPL), 256, smem64>>>((const float*)pT1, G2, 1024);
    combine_kernel<<<(BATCH * 64 + 255) / 256, 256>>>((float*)pT2, 64);

    stage_kernel<32, 2><<<dim3(BATCH / 128, KSPL), 256, smem32>>>((const float*)pT2, G3, 1536);
    combine_kernel<<<(BATCH * 32 + 255) / 256, 256>>>(out, 32);
}

// round 3
// speedup vs baseline: 2.5611x; 2.5611x over previous
#include <cuda_runtime.h>
#include <cstdint>

#define BATCH 4096
#define RNK   64
#define DD    512

// ---------------- static device scratch ------------------------------------
__device__ uint32_t g_phiH[(size_t)BATCH * 1024];   // bf16-hi pairs, [b][cpair]
__device__ uint32_t g_phiL[(size_t)BATCH * 1024];   // bf16-lo pairs
__device__ uint32_t g_Bh1[32 * 4096 * 8];
__device__ uint32_t g_Bl1[32 * 4096 * 8];
__device__ uint32_t g_Bh2[32 * 4096 * 8];
__device__ uint32_t g_Bl2[32 * 4096 * 8];
__device__ uint32_t g_Bh3[32 * 2048 * 8];
__device__ uint32_t g_Bl3[32 * 2048 * 8];
__device__ float g_R0[BATCH * RNK];
__device__ float g_t1[BATCH * RNK];
__device__ float g_t2[BATCH * RNK];
__device__ float g_part[(size_t)32 * BATCH * RNK];  // split partials (max 32 groups)

// ---------------- helpers ---------------------------------------------------
__device__ __forceinline__ uint32_t smem_u32(const void* p) {
    uint32_t a;
    asm("{ .reg .u64 t; cvta.to.shared.u64 t, %1; cvt.u32.u64 %0, t; }"
        : "=r"(a) : "l"(p));
    return a;
}
// pack: low half = bf16(lo), high half = bf16(hi)
__device__ __forceinline__ uint32_t pack_bf16(float lo, float hi) {
    uint32_t r;
    asm("cvt.rn.bf16x2.f32 %0, %1, %2;" : "=r"(r) : "f"(hi), "f"(lo));
    return r;
}
__device__ __forceinline__ float bf16lo_f(uint32_t u) { return __uint_as_float(u << 16); }
__device__ __forceinline__ float bf16hi_f(uint32_t u) { return __uint_as_float(u & 0xFFFF0000u); }

#define CP_ASYNC16(dst, src) \
    asm volatile("cp.async.cg.shared.global [%0], [%1], 16;" :: "r"(dst), "l"(src) : "memory")
#define CP_COMMIT() asm volatile("cp.async.commit_group;" ::: "memory")
#define CP_WAIT(n)  asm volatile("cp.async.wait_group %0;" :: "n"(n) : "memory")

__device__ __forceinline__ void mma_bf16(float* c, const uint32_t* a, const uint32_t* b) {
    asm volatile(
        "mma.sync.aligned.m16n8k16.row.col.f32.bf16.bf16.f32 "
        "{%0,%1,%2,%3},{%4,%5,%6,%7},{%8,%9},{%0,%1,%2,%3};"
        : "+f"(c[0]), "+f"(c[1]), "+f"(c[2]), "+f"(c[3])
        : "r"(a[0]), "r"(a[1]), "r"(a[2]), "r"(a[3]), "r"(b[0]), "r"(b[1]));
}

// ---------------------------------------------------------------------------
// phi kernel: phi[b][c] = exp(-max(sq,0)*exp(-2 ls[c])), emitted as packed
// bf16 hi/lo pair planes: g_phiH/g_phiL [b][cpair].
// ---------------------------------------------------------------------------
__global__ __launch_bounds__(256) void phi_kernel(const float* __restrict__ X,
                                                  const float* __restrict__ Cn,
                                                  const float* __restrict__ LS)
{
    __shared__ float XsT[32][64];
    __shared__ float CsT[32][64];
    __shared__ float xn[64], cn[64], sg[64];
    const int t  = threadIdx.x;
    const int c0 = blockIdx.x * 64;
    const int b0 = blockIdx.y * 64;

    for (int x = t; x < 64 * 32; x += 256) {
        int r = x >> 5, k = x & 31;
        XsT[k][r] = X[(b0 + r) * 32 + k];
        CsT[k][r] = Cn[(c0 + r) * 32 + k];
    }
    if (t < 64) sg[t] = __expf(-2.0f * LS[c0 + t]);
    __syncthreads();
    if (t < 64) {
        float s = 0.f;
        #pragma unroll
        for (int k = 0; k < 32; k++) { float v = XsT[k][t]; s += v * v; }
        xn[t] = s;
    } else if (t < 128) {
        int c = t - 64; float s = 0.f;
        #pragma unroll
        for (int k = 0; k < 32; k++) { float v = CsT[k][c]; s += v * v; }
        cn[c] = s;
    }
    __syncthreads();

    const int tc = (t & 15) * 4;   // 4 consecutive centres
    const int tb = (t >> 4) * 4;   // 4 batch rows
    float acc[4][4];               // [ci][bi]
    #pragma unroll
    for (int i = 0; i < 4; i++)
        #pragma unroll
        for (int j = 0; j < 4; j++) acc[i][j] = 0.f;

    #pragma unroll
    for (int k = 0; k < 32; k++) {
        float4 xv = *reinterpret_cast<const float4*>(&XsT[k][tb]);
        float4 cv = *reinterpret_cast<const float4*>(&CsT[k][tc]);
        float xa[4] = {xv.x, xv.y, xv.z, xv.w};
        float ca[4] = {cv.x, cv.y, cv.z, cv.w};
        #pragma unroll
        for (int ci = 0; ci < 4; ci++)
            #pragma unroll
            for (int bi = 0; bi < 4; bi++)
                acc[ci][bi] += ca[ci] * xa[bi];
    }

    #pragma unroll
    for (int bi = 0; bi < 4; bi++) {
        float o[4];
        #pragma unroll
        for (int ci = 0; ci < 4; ci++) {
            float sq = fmaxf(xn[tb + bi] + cn[tc + ci] - 2.0f * acc[ci][bi], 0.0f);
            o[ci] = __expf(-sq * sg[tc + ci]);
        }
        uint32_t h01 = pack_bf16(o[0], o[1]);
        uint32_t h23 = pack_bf16(o[2], o[3]);
        uint32_t l01 = pack_bf16(o[0] - bf16lo_f(h01), o[1] - bf16hi_f(h01));
        uint32_t l23 = pack_bf16(o[2] - bf16lo_f(h23), o[3] - bf16hi_f(h23));
        size_t base = (size_t)(b0 + tb + bi) * 1024 + ((c0 + tc) >> 1);
        *reinterpret_cast<uint2*>(&g_phiH[base]) = make_uint2(h01, h23);
        *reinterpret_cast<uint2*>(&g_phiL[base]) = make_uint2(l01, l23);
    }
}

// ---------------------------------------------------------------------------
// Pack B: G[i][d][j] (fp32) -> bf16 hi/lo pair planes [kt][n][w],
// n = i*NOUT + j, word w covers d-pair (kt*16+2w, +1), low = even d.
// ---------------------------------------------------------------------------
template<int NOUT>
__global__ __launch_bounds__(256) void packB(const float* __restrict__ G,
                                             uint32_t* __restrict__ Bh,
                                             uint32_t* __restrict__ Bl)
{
    const int NB = NOUT * 64;
    int idx = blockIdx.x * 256 + threadIdx.x;   // over NB*8
    int kt = blockIdx.y;
    int n = idx >> 3, w = idx & 7;
    int i = n / NOUT, j = n - i * NOUT;
    int d = kt * 16 + w * 2;
    float g0 = G[((size_t)i * DD + d) * NOUT + j];
    float g1 = G[((size_t)i * DD + d + 1) * NOUT + j];
    uint32_t h = pack_bf16(g0, g1);
    uint32_t l = pack_bf16(g0 - bf16lo_f(h), g1 - bf16hi_f(h));
    Bh[((size_t)kt * NB + n) * 8 + w] = h;
    Bl[((size_t)kt * NB + n) * 8 + w] = l;
}

// ---------------------------------------------------------------------------
// R0 = Phi0 @ G0 : M=4096,N=64,K=512 (FFMA; small). Phi reconstructed hi+lo.
// ---------------------------------------------------------------------------
__global__ __launch_bounds__(256) void r0_kernel(const float* __restrict__ G0)
{
    __shared__ float As[32][64];
    __shared__ float Bs[32][64];
    const int t  = threadIdx.x;
    const int b0 = blockIdx.x * 64;
    const int tb = (t & 15) * 4;
    const int tj = (t >> 4) * 4;
    float acc[4][4] = {};

    for (int d0 = 0; d0 < DD; d0 += 32) {
        __syncthreads();
        {   // stage A from packed phi (pairs d0/2 .. d0/2+15)
            int b = t >> 2, pq = t & 3;
            size_t base = (size_t)(b0 + b) * 1024 + (d0 >> 1) + pq * 4;
            uint4 h4 = *reinterpret_cast<const uint4*>(&g_phiH[base]);
            uint4 l4 = *reinterpret_cast<const uint4*>(&g_phiL[base]);
            uint32_t hh[4] = {h4.x, h4.y, h4.z, h4.w};
            uint32_t ll[4] = {l4.x, l4.y, l4.z, l4.w};
            #pragma unroll
            for (int q = 0; q < 4; q++) {
                As[pq * 8 + q * 2 + 0][b] = bf16lo_f(hh[q]) + bf16lo_f(ll[q]);
                As[pq * 8 + q * 2 + 1][b] = bf16hi_f(hh[q]) + bf16hi_f(ll[q]);
            }
        }
        for (int x = t; x < 32 * 64; x += 256) {
            int k = x >> 6, r = x & 63;
            Bs[k][r] = G0[(d0 + k) * RNK + r];
        }
        __syncthreads();
        #pragma unroll
        for (int k = 0; k < 32; k++) {
            float4 a = *reinterpret_cast<const float4*>(&As[k][tb]);
            float4 b = *reinterpret_cast<const float4*>(&Bs[k][tj]);
            float aa[4] = {a.x, a.y, a.z, a.w};
            float bb[4] = {b.x, b.y, b.z, b.w};
            #pragma unroll
            for (int bi = 0; bi < 4; bi++)
                #pragma unroll
                for (int ji = 0; ji < 4; ji++)
                    acc[bi][ji] += aa[bi] * bb[ji];
        }
    }
    #pragma unroll
    for (int bi = 0; bi < 4; bi++)
        #pragma unroll
        for (int ji = 0; ji < 4; ji++)
            g_R0[(b0 + tb + bi) * RNK + tj + ji] = acc[bi][ji];
}

// ---------------------------------------------------------------------------
// Stage GEMM (mma.sync bf16 x3): H[b, n=(i,j)] = sum_d Phi[b,d] B[d,n],
// epilogue folds: part[g][b][j] = sum_{i in block} V[b,i] * H[b,(i,j)].
// Block tile 128m x 128n, K=512 (32 k16 steps), 8 warps (2m x 4n), warp 64x32.
// 4-stage cp.async pipeline. SMEM rows padded to 12 words (conflict-free).
// ---------------------------------------------------------------------------
template<int NOUT>
__global__ __launch_bounds__(256, 1) void stage_mma(const float* __restrict__ V,
                                                    const uint32_t* __restrict__ BhG,
                                                    const uint32_t* __restrict__ BlG,
                                                    int cpair0)
{
    const int NB = NOUT * 64;
    extern __shared__ uint32_t sm[];          // 4 bufs x (Ah,Al,Bh,Bl) x 128x12
    const uint32_t smb = smem_u32(sm);

    const int t    = threadIdx.x;
    const int lane = t & 31;
    const int wid  = t >> 5;
    const int wm   = wid >> 2;                // 0..1
    const int wn   = wid & 3;                 // 0..3
    const int g    = lane >> 2;
    const int tg   = lane & 3;
    const int b0   = blockIdx.x * 128;
    const int nb0  = blockIdx.y * 128;

    const int row  = t >> 1;                  // 0..127 (for cp.async)
    const int half = t & 1;

    // per-thread gmem srcs (advance kt*8 words each step)
    const uint32_t* srcAh = g_phiH + (size_t)(b0 + row) * 1024 + cpair0 + half * 4;
    const uint32_t* srcAl = g_phiL + (size_t)(b0 + row) * 1024 + cpair0 + half * 4;
    const uint32_t* srcBh = BhG + ((size_t)(nb0 + row)) * 8 + half * 4;
    const uint32_t* srcBl = BlG + ((size_t)(nb0 + row)) * 8 + half * 4;
    const uint32_t dstA = smb + (row * 12 + half * 4) * 4;

    float acc[4][4][4];
    #pragma unroll
    for (int a = 0; a < 4; a++)
        #pragma unroll
        for (int b = 0; b < 4; b++)
            #pragma unroll
            for (int c = 0; c < 4; c++) acc[a][b][c] = 0.f;

    // prologue: issue kt = 0,1,2
    #pragma unroll
    for (int kt = 0; kt < 3; kt++) {
        uint32_t bb = (uint32_t)(kt & 3) * 24576u;  // 6144 words * 4B
        CP_ASYNC16(dstA + bb,                  srcAh + kt * 8);
        CP_ASYNC16(dstA + bb + 6144,           srcAl + kt * 8);
        CP_ASYNC16(dstA + bb + 12288,          srcBh + (size_t)kt * NB * 8);
        CP_ASYNC16(dstA + bb + 18432,          srcBl + (size_t)kt * NB * 8);
        CP_COMMIT();
    }

    for (int kt = 0; kt < 32; kt++) {
        if (kt < 30)      CP_WAIT(2);
        else if (kt == 30) CP_WAIT(1);
        else               CP_WAIT(0);
        __syncthreads();

        const uint32_t* Ah = sm + (kt & 3) * 6144;
        const uint32_t* Al = Ah + 1536;
        const uint32_t* Bh = Ah + 3072;
        const uint32_t* Bl = Ah + 4608;

        uint32_t ah[4][4], al[4][4], bh[4][2], bl[4][2];
        #pragma unroll
        for (int mf = 0; mf < 4; mf++) {
            int r = wm * 64 + mf * 16 + g;
            ah[mf][0] = Ah[r * 12 + tg];
            ah[mf][1] = Ah[(r + 8) * 12 + tg];
            ah[mf][2] = Ah[r * 12 + tg + 4];
            ah[mf][3] = Ah[(r + 8) * 12 + tg + 4];
            al[mf][0] = Al[r * 12 + tg];
            al[mf][1] = Al[(r + 8) * 12 + tg];
            al[mf][2] = Al[r * 12 + tg + 4];
            al[mf][3] = Al[(r + 8) * 12 + tg + 4];
        }
        #pragma unroll
        for (int nf = 0; nf < 4; nf++) {
            int n = wn * 32 + nf * 8 + g;
            bh[nf][0] = Bh[n * 12 + tg];
            bh[nf][1] = Bh[n * 12 + tg + 4];
            bl[nf][0] = Bl[n * 12 + tg];
            bl[nf][1] = Bl[n * 12 + tg + 4];
        }
        #pragma unroll
        for (int mf = 0; mf < 4; mf++)
            #pragma unroll
            for (int nf = 0; nf < 4; nf++) {
                mma_bf16(acc[mf][nf], ah[mf], bh[nf]);
                mma_bf16(acc[mf][nf], ah[mf], bl[nf]);
                mma_bf16(acc[mf][nf], al[mf], bh[nf]);
            }

        int kn = kt + 3;
        if (kn < 32) {
            uint32_t bb = (uint32_t)(kn & 3) * 24576u;
            CP_ASYNC16(dstA + bb,         srcAh + kn * 8);
            CP_ASYNC16(dstA + bb + 6144,  srcAl + kn * 8);
            CP_ASYNC16(dstA + bb + 12288, srcBh + (size_t)kn * NB * 8);
            CP_ASYNC16(dstA + bb + 18432, srcBl + (size_t)kn * NB * 8);
            CP_COMMIT();
        }
    }
    __syncthreads();

    // ---- epilogue: scale by V[b,i], fold i within block, write partial ----
    float* red = reinterpret_cast<float*>(sm);
    constexpr int RP = (NOUT == 64) ? 72 : 36;   // padded row stride

    const int iloc   = (NOUT == 64) ? (wn >> 1) : wn;
    const int iglob  = blockIdx.y * (128 / NOUT) + iloc;
    const int jb     = (NOUT == 64) ? ((wn & 1) * 32) : 0;

    float vv[4][2];
    #pragma unroll
    for (int mf = 0; mf < 4; mf++) {
        int r = b0 + wm * 64 + mf * 16 + g;
        vv[mf][0] = V[(size_t)r * RNK + iglob];
        vv[mf][1] = V[(size_t)(r + 8) * RNK + iglob];
    }

    const int nphase = (NOUT == 64) ? 2 : 4;
    const int wpp    = (NOUT == 64) ? 2 : 1;     // warps (wn) per phase
    #pragma unroll
    for (int ph = 0; ph < 4; ph++) {
        if (ph < nphase) {
            if (wn / wpp == ph) {
                #pragma unroll
                for (int mf = 0; mf < 4; mf++) {
                    int r = wm * 64 + mf * 16 + g;
                    #pragma unroll
                    for (int nf = 0; nf < 4; nf++) {
                        int j = jb + nf * 8 + tg * 2;
                        if (ph == 0) {
                            red[r * RP + j]           = acc[mf][nf][0] * vv[mf][0];
                            red[r * RP + j + 1]       = acc[mf][nf][1] * vv[mf][0];
                            red[(r + 8) * RP + j]     = acc[mf][nf][2] * vv[mf][1];
                            red[(r + 8) * RP + j + 1] = acc[mf][nf][3] * vv[mf][1];
                        } else {
                            red[r * RP + j]           += acc[mf][nf][0] * vv[mf][0];
                            red[r * RP + j + 1]       += acc[mf][nf][1] * vv[mf][0];
                            red[(r + 8) * RP + j]     += acc[mf][nf][2] * vv[mf][1];
                            red[(r + 8) * RP + j + 1] += acc[mf][nf][3] * vv[mf][1];
                        }
                    }
                }
            }
            __syncthreads();
        }
    }

    float* outp = g_part + (size_t)blockIdx.y * ((size_t)BATCH * NOUT);
    for (int x = t; x < 128 * NOUT; x += 256) {
        int r = x / NOUT, j = x % NOUT;
        outp[(size_t)(b0 + r) * NOUT + j] = red[r * RP + j];
    }
}

// ---------------------------------------------------------------------------
__global__ void combine_kernel(float* __restrict__ dst, int ng, int nout)
{
    int n = BATCH * nout;
    int x = blockIdx.x * blockDim.x + threadIdx.x;
    if (x < n) {
        float s = 0.f;
        for (int g = 0; g < ng; g++) s += g_part[(size_t)g * n + x];
        dst[x] = s;
    }
}

// ---------------------------------------------------------------------------
extern "C" void kernel_launch(void* const* d_in, const int* in_sizes, int n_in,
                              void* d_out, int out_size)
{
    const float* X  = (const float*)d_in[0];
    const float* Cn = (const float*)d_in[1];
    const float* LS = (const float*)d_in[2];
    const float* G0 = (const float*)d_in[3];
    const float* G1 = (const float*)d_in[4];
    const float* G2 = (const float*)d_in[5];
    const float* G3 = (const float*)d_in[6];
    float* out = (float*)d_out;

    void *pR0, *pT1, *pT2, *pBh1, *pBl1, *pBh2, *pBl2, *pBh3, *pBl3;
    cudaGetSymbolAddress(&pR0, g_R0);
    cudaGetSymbolAddress(&pT1, g_t1);
    cudaGetSymbolAddress(&pT2, g_t2);
    cudaGetSymbolAddress(&pBh1, g_Bh1);
    cudaGetSymbolAddress(&pBl1, g_Bl1);
    cudaGetSymbolAddress(&pBh2, g_Bh2);
    cudaGetSymbolAddress(&pBl2, g_Bl2);
    cudaGetSymbolAddress(&pBh3, g_Bh3);
    cudaGetSymbolAddress(&pBl3, g_Bl3);

    const int smemStage = 4 * 6144 * 4;   // 98304 B
    static int s_init = 0;
    if (!s_init) {
        cudaFuncSetAttribute(stage_mma<64>, cudaFuncAttributeMaxDynamicSharedMemorySize, smemStage);
        cudaFuncSetAttribute(stage_mma<32>, cudaFuncAttributeMaxDynamicSharedMemorySize, smemStage);
        s_init = 1;
    }

    phi_kernel<<<dim3(2048 / 64, BATCH / 64), 256>>>(X, Cn, LS);
    packB<64><<<dim3(4096 * 8 / 256, 32), 256>>>(G1, (uint32_t*)pBh1, (uint32_t*)pBl1);
    packB<64><<<dim3(4096 * 8 / 256, 32), 256>>>(G2, (uint32_t*)pBh2, (uint32_t*)pBl2);
    packB<32><<<dim3(2048 * 8 / 256, 32), 256>>>(G3, (uint32_t*)pBh3, (uint32_t*)pBl3);
    r0_kernel<<<BATCH / 64, 256>>>(G0);

    stage_mma<64><<<dim3(BATCH / 128, 32), 256, smemStage>>>(
        (const float*)pR0, (const uint32_t*)pBh1, (const uint32_t*)pBl1, 256);
    combine_kernel<<<(BATCH * 64 + 255) / 256, 256>>>((float*)pT1, 32, 64);

    stage_mma<64><<<dim3(BATCH / 128, 32), 256, smemStage>>>(
        (const float*)pT1, (const uint32_t*)pBh2, (const uint32_t*)pBl2, 512);
    combine_kernel<<<(BATCH * 64 + 255) / 256, 256>>>((float*)pT2, 32, 64);

    stage_mma<32><<<dim3(BATCH / 128, 16), 256, smemStage>>>(
        (const float*)pT2, (const uint32_t*)pBh3, (const uint32_t*)pBl3, 768);
    combine_kernel<<<(BATCH * 32 + 255) / 256, 256>>>(out, 16, 32);
}

// round 4
// speedup vs baseline: 3.6617x; 1.4298x over previous
#include <cuda_runtime.h>
#include <cstdint>

#define BATCH 4096
#define RNK   64
#define DD    512

// ---------------- static device scratch ------------------------------------
__device__ uint32_t g_phiH[(size_t)BATCH * 1024];   // bf16-hi pairs, [b][cpair]
__device__ uint32_t g_phiL[(size_t)BATCH * 1024];   // bf16-lo pairs
__device__ uint32_t g_Bh1[32 * 4096 * 8];
__device__ uint32_t g_Bh2[32 * 4096 * 8];
__device__ uint32_t g_Bh3[32 * 2048 * 8];
__device__ float g_R0[BATCH * RNK];
__device__ float g_t1[BATCH * RNK];
__device__ float g_t2[BATCH * RNK];
__device__ float g_part[(size_t)32 * BATCH * RNK];

// ---------------- helpers ---------------------------------------------------
__device__ __forceinline__ uint32_t smem_u32(const void* p) {
    uint32_t a;
    asm("{ .reg .u64 t; cvta.to.shared.u64 t, %1; cvt.u32.u64 %0, t; }"
        : "=r"(a) : "l"(p));
    return a;
}
__device__ __forceinline__ uint32_t pack_bf16(float lo, float hi) {
    uint32_t r;
    asm("cvt.rn.bf16x2.f32 %0, %1, %2;" : "=r"(r) : "f"(hi), "f"(lo));
    return r;
}
__device__ __forceinline__ float bf16lo_f(uint32_t u) { return __uint_as_float(u << 16); }
__device__ __forceinline__ float bf16hi_f(uint32_t u) { return __uint_as_float(u & 0xFFFF0000u); }

#define CP_ASYNC16(dst, src) \
    asm volatile("cp.async.cg.shared.global [%0], [%1], 16;" :: "r"(dst), "l"(src) : "memory")
#define CP_COMMIT() asm volatile("cp.async.commit_group;" ::: "memory")
#define CP_WAIT(n)  asm volatile("cp.async.wait_group %0;" :: "n"(n) : "memory")

#define LDSM_X4(r0, r1, r2, r3, addr) \
    asm volatile("ldmatrix.sync.aligned.m8n8.x4.shared.b16 {%0,%1,%2,%3}, [%4];" \
        : "=r"(r0), "=r"(r1), "=r"(r2), "=r"(r3) : "r"(addr))

__device__ __forceinline__ void mma_bf16(float* c, const uint32_t* a, const uint32_t* b) {
    asm volatile(
        "mma.sync.aligned.m16n8k16.row.col.f32.bf16.bf16.f32 "
        "{%0,%1,%2,%3},{%4,%5,%6,%7},{%8,%9},{%0,%1,%2,%3};"
        : "+f"(c[0]), "+f"(c[1]), "+f"(c[2]), "+f"(c[3])
        : "r"(a[0]), "r"(a[1]), "r"(a[2]), "r"(a[3]), "r"(b[0]), "r"(b[1]));
}

// ---------------------------------------------------------------------------
// phi kernel: phi[b][c] = exp(-max(sq,0)*exp(-2 ls[c])) -> bf16 hi/lo planes
// ---------------------------------------------------------------------------
__global__ __launch_bounds__(256) void phi_kernel(const float* __restrict__ X,
                                                  const float* __restrict__ Cn,
                                                  const float* __restrict__ LS)
{
    __shared__ float XsT[32][64];
    __shared__ float CsT[32][64];
    __shared__ float xn[64], cn[64], sg[64];
    const int t  = threadIdx.x;
    const int c0 = blockIdx.x * 64;
    const int b0 = blockIdx.y * 64;

    for (int x = t; x < 64 * 32; x += 256) {
        int r = x >> 5, k = x & 31;
        XsT[k][r] = X[(b0 + r) * 32 + k];
        CsT[k][r] = Cn[(c0 + r) * 32 + k];
    }
    if (t < 64) sg[t] = __expf(-2.0f * LS[c0 + t]);
    __syncthreads();
    if (t < 64) {
        float s = 0.f;
        #pragma unroll
        for (int k = 0; k < 32; k++) { float v = XsT[k][t]; s += v * v; }
        xn[t] = s;
    } else if (t < 128) {
        int c = t - 64; float s = 0.f;
        #pragma unroll
        for (int k = 0; k < 32; k++) { float v = CsT[k][c]; s += v * v; }
        cn[c] = s;
    }
    __syncthreads();

    const int tc = (t & 15) * 4;
    const int tb = (t >> 4) * 4;
    float acc[4][4];
    #pragma unroll
    for (int i = 0; i < 4; i++)
        #pragma unroll
        for (int j = 0; j < 4; j++) acc[i][j] = 0.f;

    #pragma unroll
    for (int k = 0; k < 32; k++) {
        float4 xv = *reinterpret_cast<const float4*>(&XsT[k][tb]);
        float4 cv = *reinterpret_cast<const float4*>(&CsT[k][tc]);
        float xa[4] = {xv.x, xv.y, xv.z, xv.w};
        float ca[4] = {cv.x, cv.y, cv.z, cv.w};
        #pragma unroll
        for (int ci = 0; ci < 4; ci++)
            #pragma unroll
            for (int bi = 0; bi < 4; bi++)
                acc[ci][bi] += ca[ci] * xa[bi];
    }

    #pragma unroll
    for (int bi = 0; bi < 4; bi++) {
        float o[4];
        #pragma unroll
        for (int ci = 0; ci < 4; ci++) {
            float sq = fmaxf(xn[tb + bi] + cn[tc + ci] - 2.0f * acc[ci][bi], 0.0f);
            o[ci] = __expf(-sq * sg[tc + ci]);
        }
        uint32_t h01 = pack_bf16(o[0], o[1]);
        uint32_t h23 = pack_bf16(o[2], o[3]);
        uint32_t l01 = pack_bf16(o[0] - bf16lo_f(h01), o[1] - bf16hi_f(h01));
        uint32_t l23 = pack_bf16(o[2] - bf16lo_f(h23), o[3] - bf16hi_f(h23));
        size_t base = (size_t)(b0 + tb + bi) * 1024 + ((c0 + tc) >> 1);
        *reinterpret_cast<uint2*>(&g_phiH[base]) = make_uint2(h01, h23);
        *reinterpret_cast<uint2*>(&g_phiL[base]) = make_uint2(l01, l23);
    }
}

// ---------------------------------------------------------------------------
// Pack B (hi only): G[i][d][j] -> [kt][n][w] bf16 d-pairs, n = i*NOUT+j
// ---------------------------------------------------------------------------
template<int NOUT>
__global__ __launch_bounds__(256) void packB(const float* __restrict__ G,
                                             uint32_t* __restrict__ Bh)
{
    const int NB = NOUT * 64;
    int idx = blockIdx.x * 256 + threadIdx.x;
    int kt = blockIdx.y;
    int n = idx >> 3, w = idx & 7;
    int i = n / NOUT, j = n - i * NOUT;
    int d = kt * 16 + w * 2;
    float g0 = G[((size_t)i * DD + d) * NOUT + j];
    float g1 = G[((size_t)i * DD + d + 1) * NOUT + j];
    Bh[((size_t)kt * NB + n) * 8 + w] = pack_bf16(g0, g1);
}

// ---------------------------------------------------------------------------
// R0 = Phi0 @ G0 (FFMA, small)
// ---------------------------------------------------------------------------
__global__ __launch_bounds__(256) void r0_kernel(const float* __restrict__ G0)
{
    __shared__ float As[32][64];
    __shared__ float Bs[32][64];
    const int t  = threadIdx.x;
    const int b0 = blockIdx.x * 64;
    const int tb = (t & 15) * 4;
    const int tj = (t >> 4) * 4;
    float acc[4][4] = {};

    for (int d0 = 0; d0 < DD; d0 += 32) {
        __syncthreads();
        {
            int b = t >> 2, pq = t & 3;
            size_t base = (size_t)(b0 + b) * 1024 + (d0 >> 1) + pq * 4;
            uint4 h4 = *reinterpret_cast<const uint4*>(&g_phiH[base]);
            uint4 l4 = *reinterpret_cast<const uint4*>(&g_phiL[base]);
            uint32_t hh[4] = {h4.x, h4.y, h4.z, h4.w};
            uint32_t ll[4] = {l4.x, l4.y, l4.z, l4.w};
            #pragma unroll
            for (int q = 0; q < 4; q++) {
                As[pq * 8 + q * 2 + 0][b] = bf16lo_f(hh[q]) + bf16lo_f(ll[q]);
                As[pq * 8 + q * 2 + 1][b] = bf16hi_f(hh[q]) + bf16hi_f(ll[q]);
            }
        }
        for (int x = t; x < 32 * 64; x += 256) {
            int k = x >> 6, r = x & 63;
            Bs[k][r] = G0[(d0 + k) * RNK + r];
        }
        __syncthreads();
        #pragma unroll
        for (int k = 0; k < 32; k++) {
            float4 a = *reinterpret_cast<const float4*>(&As[k][tb]);
            float4 b = *reinterpret_cast<const float4*>(&Bs[k][tj]);
            float aa[4] = {a.x, a.y, a.z, a.w};
            float bb[4] = {b.x, b.y, b.z, b.w};
            #pragma unroll
            for (int bi = 0; bi < 4; bi++)
                #pragma unroll
                for (int ji = 0; ji < 4; ji++)
                    acc[bi][ji] += aa[bi] * bb[ji];
        }
    }
    #pragma unroll
    for (int bi = 0; bi < 4; bi++)
        #pragma unroll
        for (int ji = 0; ji < 4; ji++)
            g_R0[(b0 + tb + bi) * RNK + tj + ji] = acc[bi][ji];
}

// ---------------------------------------------------------------------------
// Stage GEMM (mma.sync bf16, 2-term: Ah*Bh + Al*Bh):
// H[b,(i,j)] = sum_d Phi[b,d] B[d,(i,j)]; epilogue folds V.
// Block 128m x 128n, 32 k16 steps, 8 warps (2m x 4n), ldmatrix fragment loads.
// SMEM: 4 bufs x (Ah | Al | Bh), rows padded to 12 words.
// ---------------------------------------------------------------------------
template<int NOUT>
__global__ __launch_bounds__(256, 1) void stage_mma(const float* __restrict__ V,
                                                    const uint32_t* __restrict__ BhG,
                                                    int cpair0)
{
    const int NB = NOUT * 64;
    constexpr uint32_t BUFB = 4608u * 4u;      // bytes per pipeline buffer
    extern __shared__ uint32_t sm[];
    const uint32_t smb = smem_u32(sm);

    const int t    = threadIdx.x;
    const int lane = t & 31;
    const int wid  = t >> 5;
    const int wm   = wid >> 2;
    const int wn   = wid & 3;
    const int g    = lane >> 2;
    const int tg   = lane & 3;
    const int b0   = blockIdx.x * 128;
    const int nb0  = blockIdx.y * 128;

    const int row  = t >> 1;
    const int half = t & 1;

    const uint32_t* srcAh = g_phiH + (size_t)(b0 + row) * 1024 + cpair0 + half * 4;
    const uint32_t* srcAl = g_phiL + (size_t)(b0 + row) * 1024 + cpair0 + half * 4;
    const uint32_t* srcBh = BhG + ((size_t)(nb0 + row)) * 8 + half * 4;
    const uint32_t dstA = smb + (row * 12 + half * 4) * 4;

    // ldmatrix per-lane offsets (bytes, within a buffer)
    const int rr  = lane & 7;
    const int sub = lane >> 3;
    const uint32_t aoff = (uint32_t)(((wm * 64 + rr + ((sub & 1) << 3)) * 12 +
                                      ((sub >> 1) << 2)) * 4);
    const uint32_t boff = (uint32_t)(((wn * 32 + ((sub >> 1) << 3) + rr) * 12 +
                                      ((sub & 1) << 2)) * 4);

    float acc[4][4][4];
    #pragma unroll
    for (int a = 0; a < 4; a++)
        #pragma unroll
        for (int b = 0; b < 4; b++)
            #pragma unroll
            for (int c = 0; c < 4; c++) acc[a][b][c] = 0.f;

    #pragma unroll
    for (int kt = 0; kt < 3; kt++) {
        uint32_t bb = (uint32_t)kt * BUFB;
        CP_ASYNC16(dstA + bb,         srcAh + kt * 8);
        CP_ASYNC16(dstA + bb + 6144,  srcAl + kt * 8);
        CP_ASYNC16(dstA + bb + 12288, srcBh + (size_t)kt * NB * 8);
        CP_COMMIT();
    }

    for (int kt = 0; kt < 32; kt++) {
        if (kt < 30)       CP_WAIT(2);
        else if (kt == 30) CP_WAIT(1);
        else               CP_WAIT(0);
        __syncthreads();

        const uint32_t base = smb + (uint32_t)(kt & 3) * BUFB;

        uint32_t ah[4][4], al[4][4], bh[4][2];
        #pragma unroll
        for (int mf = 0; mf < 4; mf++) {
            LDSM_X4(ah[mf][0], ah[mf][1], ah[mf][2], ah[mf][3], base + aoff + mf * 768u);
            LDSM_X4(al[mf][0], al[mf][1], al[mf][2], al[mf][3], base + 6144u + aoff + mf * 768u);
        }
        LDSM_X4(bh[0][0], bh[0][1], bh[1][0], bh[1][1], base + 12288u + boff);
        LDSM_X4(bh[2][0], bh[2][1], bh[3][0], bh[3][1], base + 12288u + boff + 768u);

        #pragma unroll
        for (int mf = 0; mf < 4; mf++)
            #pragma unroll
            for (int nf = 0; nf < 4; nf++) {
                mma_bf16(acc[mf][nf], ah[mf], bh[nf]);
                mma_bf16(acc[mf][nf], al[mf], bh[nf]);
            }

        int kn = kt + 3;
        if (kn < 32) {
            uint32_t bb = (uint32_t)(kn & 3) * BUFB;
            CP_ASYNC16(dstA + bb,         srcAh + kn * 8);
            CP_ASYNC16(dstA + bb + 6144,  srcAl + kn * 8);
            CP_ASYNC16(dstA + bb + 12288, srcBh + (size_t)kn * NB * 8);
            CP_COMMIT();
        }
    }
    __syncthreads();

    // ---- epilogue: scale by V[b,i], fold i within block, write partial ----
    float* red = reinterpret_cast<float*>(sm);
    constexpr int RP = (NOUT == 64) ? 72 : 36;

    const int iloc  = (NOUT == 64) ? (wn >> 1) : wn;
    const int iglob = blockIdx.y * (128 / NOUT) + iloc;
    const int jb    = (NOUT == 64) ? ((wn & 1) * 32) : 0;

    float vv[4][2];
    #pragma unroll
    for (int mf = 0; mf < 4; mf++) {
        int r = b0 + wm * 64 + mf * 16 + g;
        vv[mf][0] = V[(size_t)r * RNK + iglob];
        vv[mf][1] = V[(size_t)(r + 8) * RNK + iglob];
    }

    const int nphase = (NOUT == 64) ? 2 : 4;
    const int wpp    = (NOUT == 64) ? 2 : 1;
    #pragma unroll
    for (int ph = 0; ph < 4; ph++) {
        if (ph < nphase) {
            if (wn / wpp == ph) {
                #pragma unroll
                for (int mf = 0; mf < 4; mf++) {
                    int r = wm * 64 + mf * 16 + g;
                    #pragma unroll
                    for (int nf = 0; nf < 4; nf++) {
                        int j = jb + nf * 8 + tg * 2;
                        if (ph == 0) {
                            red[r * RP + j]           = acc[mf][nf][0] * vv[mf][0];
                            red[r * RP + j + 1]       = acc[mf][nf][1] * vv[mf][0];
                            red[(r + 8) * RP + j]     = acc[mf][nf][2] * vv[mf][1];
                            red[(r + 8) * RP + j + 1] = acc[mf][nf][3] * vv[mf][1];
                        } else {
                            red[r * RP + j]           += acc[mf][nf][0] * vv[mf][0];
                            red[r * RP + j + 1]       += acc[mf][nf][1] * vv[mf][0];
                            red[(r + 8) * RP + j]     += acc[mf][nf][2] * vv[mf][1];
                            red[(r + 8) * RP + j + 1] += acc[mf][nf][3] * vv[mf][1];
                        }
                    }
                }
            }
            __syncthreads();
        }
    }

    float* outp = g_part + (size_t)blockIdx.y * ((size_t)BATCH * NOUT);
    for (int x = t; x < 128 * NOUT; x += 256) {
        int r = x / NOUT, j = x % NOUT;
        outp[(size_t)(b0 + r) * NOUT + j] = red[r * RP + j];
    }
}

// ---------------------------------------------------------------------------
__global__ void combine_kernel(float* __restrict__ dst, int ng, int nout)
{
    int n = BATCH * nout;
    int x = blockIdx.x * blockDim.x + threadIdx.x;
    if (x < n) {
        float s = 0.f;
        for (int g = 0; g < ng; g++) s += g_part[(size_t)g * n + x];
        dst[x] = s;
    }
}

// ---------------------------------------------------------------------------
extern "C" void kernel_launch(void* const* d_in, const int* in_sizes, int n_in,
                              void* d_out, int out_size)
{
    const float* X  = (const float*)d_in[0];
    const float* Cn = (const float*)d_in[1];
    const float* LS = (const float*)d_in[2];
    const float* G0 = (const float*)d_in[3];
    const float* G1 = (const float*)d_in[4];
    const float* G2 = (const float*)d_in[5];
    const float* G3 = (const float*)d_in[6];
    float* out = (float*)d_out;

    void *pR0, *pT1, *pT2, *pBh1, *pBh2, *pBh3;
    cudaGetSymbolAddress(&pR0, g_R0);
    cudaGetSymbolAddress(&pT1, g_t1);
    cudaGetSymbolAddress(&pT2, g_t2);
    cudaGetSymbolAddress(&pBh1, g_Bh1);
    cudaGetSymbolAddress(&pBh2, g_Bh2);
    cudaGetSymbolAddress(&pBh3, g_Bh3);

    const int smemStage = 4 * 4608 * 4;   // 73728 B
    static int s_init = 0;
    if (!s_init) {
        cudaFuncSetAttribute(stage_mma<64>, cudaFuncAttributeMaxDynamicSharedMemorySize, smemStage);
        cudaFuncSetAttribute(stage_mma<32>, cudaFuncAttributeMaxDynamicSharedMemorySize, smemStage);
        s_init = 1;
    }

    phi_kernel<<<dim3(2048 / 64, BATCH / 64), 256>>>(X, Cn, LS);
    packB<64><<<dim3(4096 * 8 / 256, 32), 256>>>(G1, (uint32_t*)pBh1);
    packB<64><<<dim3(4096 * 8 / 256, 32), 256>>>(G2, (uint32_t*)pBh2);
    packB<32><<<dim3(2048 * 8 / 256, 32), 256>>>(G3, (uint32_t*)pBh3);
    r0_kernel<<<BATCH / 64, 256>>>(G0);

    stage_mma<64><<<dim3(BATCH / 128, 32), 256, smemStage>>>(
        (const float*)pR0, (const uint32_t*)pBh1, 256);
    combine_kernel<<<(BATCH * 64 + 255) / 256, 256>>>((float*)pT1, 32, 64);

    stage_mma<64><<<dim3(BATCH / 128, 32), 256, smemStage>>>(
        (const float*)pT1, (const uint32_t*)pBh2, 512);
    combine_kernel<<<(BATCH * 64 + 255) / 256, 256>>>((float*)pT2, 32, 64);

    stage_mma<32><<<dim3(BATCH / 128, 16), 256, smemStage>>>(
        (const float*)pT2, (const uint32_t*)pBh3, 768);
    combine_kernel<<<(BATCH * 32 + 255) / 256, 256>>>(out, 16, 32);
}